// round 15
// baseline (speedup 1.0000x reference)
#include <cuda_runtime.h>
#include <cuda_bf16.h>

typedef unsigned int u32;

#define S_LEN 2048
#define DIMN  512
#define NH    8
#define DH    64
#define MTOT  8192
#define NBLH  32
#define VROWS 80          // 64 d-rows + ones row (64) + 15 zero pad rows
#define QSCALE 0.04419417382415922f   // 1/sqrt(512)
#define LNC 0.14391156831212787f      // ln(10000)/64

// ---------------------------------------------------------------------------
// Scratch (allocation-free device globals), bf16 hi/lo pairs
// ---------------------------------------------------------------------------
__device__ __align__(16) __nv_bfloat16 g_xhi[MTOT * DIMN],  g_xlo[MTOT * DIMN];
__device__ __align__(16) __nv_bfloat16 g_whi[4 * DIMN * DIMN], g_wlo[4 * DIMN * DIMN];
__device__ __align__(16) __nv_bfloat16 g_qhi[NBLH * S_LEN * DH], g_qlo[NBLH * S_LEN * DH];
__device__ __align__(16) __nv_bfloat16 g_khi[NBLH * S_LEN * DH], g_klo[NBLH * S_LEN * DH];
__device__ __align__(16) __nv_bfloat16 g_vthi[NBLH * VROWS * S_LEN], g_vtlo[NBLH * VROWS * S_LEN];
__device__ __align__(16) __nv_bfloat16 g_ihi[MTOT * DIMN],  g_ilo[MTOT * DIMN];

// ---------------------------------------------------------------------------
// Helpers
// ---------------------------------------------------------------------------
__device__ __forceinline__ u32 pkbf(float a, float b) {   // a->lo, b->hi
    u32 r;
    asm("cvt.rn.bf16x2.f32 %0, %1, %2;" : "=r"(r) : "f"(b), "f"(a));
    return r;
}
__device__ __forceinline__ float bfr(float v) {
    return __bfloat162float(__float2bfloat16(v));
}
// pack high-16 bits of two floats: (hi16(b)<<16) | hi16(a) — 1 PRMT
__device__ __forceinline__ u32 prmt_hi(u32 a, u32 b) {
    u32 r;
    asm("prmt.b32 %0, %1, %2, 0x7632;" : "=r"(r) : "r"(a), "r"(b));
    return r;
}
__device__ __forceinline__ void mmab(float* d, const u32* a, u32 b0, u32 b1) {
    asm volatile(
        "mma.sync.aligned.m16n8k16.row.col.f32.bf16.bf16.f32 "
        "{%0,%1,%2,%3}, {%4,%5,%6,%7}, {%8,%9}, {%0,%1,%2,%3};"
        : "+f"(d[0]), "+f"(d[1]), "+f"(d[2]), "+f"(d[3])
        : "r"(a[0]), "r"(a[1]), "r"(a[2]), "r"(a[3]), "r"(b0), "r"(b1));
}
__device__ __forceinline__ u32 smem_u32(const void* p) {
    u32 a;
    asm("{ .reg .u64 t; cvta.to.shared.u64 t, %1; cvt.u32.u64 %0, t; }"
        : "=r"(a) : "l"(p));
    return a;
}
__device__ __forceinline__ void cpa16(u32 dst, const void* src) {
    asm volatile("cp.async.cg.shared.global [%0], [%1], 16;" :: "r"(dst), "l"(src));
}
__device__ __forceinline__ void cpcommit() {
    asm volatile("cp.async.commit_group;" ::: "memory");
}
__device__ __forceinline__ void cpwait1() {
    asm volatile("cp.async.wait_group 1;" ::: "memory");
}
__device__ __forceinline__ void cpwait0() {
    asm volatile("cp.async.wait_group 0;" ::: "memory");
}
__device__ __forceinline__ void ldsm4(u32* r, u32 a) {
    asm volatile("ldmatrix.sync.aligned.m8n8.x4.shared.b16 {%0,%1,%2,%3}, [%4];"
                 : "=r"(r[0]), "=r"(r[1]), "=r"(r[2]), "=r"(r[3]) : "r"(a));
}

// ---------------------------------------------------------------------------
// Fused prep: all fp32->bf16 hi/lo splits + V^T ones/pad rows, one launch.
// ---------------------------------------------------------------------------
__global__ __launch_bounds__(256)
void prep_kernel(const float* __restrict__ x,
                 const float* __restrict__ Wq, const float* __restrict__ Wk,
                 const float* __restrict__ Wv, const float* __restrict__ Wo)
{
    int b = blockIdx.x;
    int tid = threadIdx.x;
    if (b < 16384) {
        int i = b * 256 + tid;
        float v = x[i];
        __nv_bfloat16 h = __float2bfloat16(v);
        g_xhi[i] = h;
        g_xlo[i] = __float2bfloat16(v - __bfloat162float(h));
    } else if (b < 20480) {
        int b2 = b - 16384;
        int widx = b2 >> 10;
        int i = (b2 & 1023) * 256 + tid;
        const float* W = widx == 0 ? Wq : widx == 1 ? Wk : widx == 2 ? Wv : Wo;
        float v = W[i];
        __nv_bfloat16 h = __float2bfloat16(v);
        size_t o = (size_t)widx * DIMN * DIMN + i;
        g_whi[o] = h;
        g_wlo[o] = __float2bfloat16(v - __bfloat162float(h));
    } else {
        int idx = (b - 20480) * 256 + tid;
        int s   = idx & (S_LEN - 1);
        int rr  = (idx >> 11) & 15;
        int blh = idx >> 15;
        size_t a = ((size_t)blh * VROWS + 64 + rr) * S_LEN + s;
        g_vthi[a] = __float2bfloat16(rr == 0 ? 1.0f : 0.0f);
        g_vtlo[a] = __float2bfloat16(0.0f);
    }
}

// ---------------------------------------------------------------------------
// Common GEMM body (R12/R14 config, untouched): tile M=128 x N=64, k-step 32,
// 3-stage cp.async, ONE barrier per k-step, ldsm-pipelined, 3-term split.
// dst_sel: 0 Q(blh,s,dh)  1 K(blh,s,dh)  2 V^T(blh,80,s)  3 fp32 out(m,512)
// ---------------------------------------------------------------------------
#define GSTAGE_B 30720     // per stage: Ah 0 | Al 10240 | Wh 20480 | Wl 25600
__device__ __forceinline__
void gemm_body(__nv_bfloat16* dsm,
               const float* __restrict__ bias,
               float* __restrict__ outp,
               int widx, int dst_sel, int do_rot, float scale, int src_sel)
{
    const __nv_bfloat16* Ahg = src_sel ? g_ihi : g_xhi;
    const __nv_bfloat16* Alg = src_sel ? g_ilo : g_xlo;
    const __nv_bfloat16* Whg = g_whi + (size_t)widx * DIMN * DIMN;
    const __nv_bfloat16* Wlg = g_wlo + (size_t)widx * DIMN * DIMN;

    const int n0 = blockIdx.x * 64;
    const int m0 = blockIdx.y * 128;
    const int tid = threadIdx.x;
    const int warp = tid >> 5, lane = tid & 31;
    const int g = lane >> 2, t = lane & 3;
    const u32 smb = smem_u32(dsm);

    const int rA = ((lane >> 3) & 1) * 8 + (lane & 7);
    const int cA = ((lane >> 4) & 1) * 8;
    const int rB = (lane >> 4) * 8 + (lane & 7);
    const int cB = ((lane >> 3) & 1) * 8;

    float acc[8][4];
    #pragma unroll
    for (int j = 0; j < 8; j++)
        #pragma unroll
        for (int d = 0; d < 4; d++) acc[j][d] = 0.f;

    auto prefetch = [&](int kt, int st) {
        u32 sb = smb + st * GSTAGE_B;
        int k0 = kt * 32;
        #pragma unroll
        for (int i = 0; i < 2; i++) {
            int idx = i * 256 + tid;
            int row = idx >> 2, c = idx & 3;
            cpa16(sb + (row * 40 + c * 8) * 2,
                  Ahg + (size_t)(m0 + row) * DIMN + k0 + c * 8);
            cpa16(sb + 10240 + (row * 40 + c * 8) * 2,
                  Alg + (size_t)(m0 + row) * DIMN + k0 + c * 8);
        }
        {
            int row = tid >> 2, c = tid & 3;
            cpa16(sb + 20480 + (row * 40 + c * 8) * 2,
                  Whg + (size_t)(n0 + row) * DIMN + k0 + c * 8);
            cpa16(sb + 25600 + (row * 40 + c * 8) * 2,
                  Wlg + (size_t)(n0 + row) * DIMN + k0 + c * 8);
        }
        cpcommit();
    };

    prefetch(0, 0);
    prefetch(1, 1);

    for (int kt = 0; kt < 16; kt++) {
        int st = kt % 3;
        if (kt < 15) cpwait1(); else cpwait0();
        __syncthreads();
        if (kt + 2 < 16) prefetch(kt + 2, (kt + 2) % 3);

        u32 sb = smb + st * GSTAGE_B;
        u32 aHb = sb + ((warp * 16 + rA) * 40 + cA) * 2;
        u32 aLb = aHb + 10240;
        u32 bHb = sb + 20480 + (rB * 40 + cB) * 2;
        u32 bLb = bHb + 5120;

        u32 ah[2][4], al[2][4];
        ldsm4(ah[0], aHb);      ldsm4(al[0], aLb);
        ldsm4(ah[1], aHb + 32); ldsm4(al[1], aLb + 32);
        u32 bh[2][4], bl[2][4];
        ldsm4(bh[0], bHb);      ldsm4(bl[0], bLb);

        #pragma unroll
        for (int idx = 0; idx < 8; idx++) {
            const int kk = idx >> 2, j2 = idx & 3;
            const int p = idx & 1;
            if (idx < 7) {
                const int ni = idx + 1, nkk = ni >> 2, nj2 = ni & 3;
                ldsm4(bh[p ^ 1], bHb + nj2 * (16 * 40 * 2) + nkk * 32);
                ldsm4(bl[p ^ 1], bLb + nj2 * (16 * 40 * 2) + nkk * 32);
            }
            mmab(acc[2 * j2],     ah[kk], bh[p][0], bh[p][1]);
            mmab(acc[2 * j2],     ah[kk], bl[p][0], bl[p][1]);
            mmab(acc[2 * j2],     al[kk], bh[p][0], bh[p][1]);
            mmab(acc[2 * j2 + 1], ah[kk], bh[p][2], bh[p][3]);
            mmab(acc[2 * j2 + 1], ah[kk], bl[p][2], bl[p][3]);
            mmab(acc[2 * j2 + 1], al[kk], bh[p][2], bh[p][3]);
        }
    }

    // ---- Epilogue ----
    const int rb = warp * 16;

    if (dst_sel == 2) {
        // V^T: transpose via smem (two passes: hi then lo)
        __nv_bfloat16* T = dsm;   // 64 x 136
        const int bl = m0 >> 11, hh = n0 >> 6;
        const int s0 = m0 & (S_LEN - 1);
        #pragma unroll
        for (int pass = 0; pass < 2; pass++) {
            __syncthreads();
            #pragma unroll
            for (int j = 0; j < 8; j++) {
                int cl0 = 8 * j + 2 * t;
                float b0 = bias[n0 + cl0], b1 = bias[n0 + cl0 + 1];
                float v00 = acc[j][0] + b0, v01 = acc[j][1] + b1;
                float v10 = acc[j][2] + b0, v11 = acc[j][3] + b1;
                float e00, e01, e10, e11;
                if (pass == 0) { e00 = v00; e01 = v01; e10 = v10; e11 = v11; }
                else { e00 = v00 - bfr(v00); e01 = v01 - bfr(v01);
                       e10 = v10 - bfr(v10); e11 = v11 - bfr(v11); }
                T[(cl0)     * 136 + rb + g]     = __float2bfloat16(e00);
                T[(cl0 + 1) * 136 + rb + g]     = __float2bfloat16(e01);
                T[(cl0)     * 136 + rb + g + 8] = __float2bfloat16(e10);
                T[(cl0 + 1) * 136 + rb + g + 8] = __float2bfloat16(e11);
            }
            __syncthreads();
            __nv_bfloat16* dst = pass ? g_vtlo : g_vthi;
            size_t base = ((size_t)(bl * NH + hh)) * VROWS * S_LEN + s0;
            #pragma unroll
            for (int w8 = 0; w8 < 4; w8++) {
                int idx = w8 * 256 + tid;
                int row = idx >> 4, c8 = idx & 15;
                *(uint4*)(dst + base + (size_t)row * S_LEN + c8 * 8) =
                    *(const uint4*)(T + row * 136 + c8 * 8);
            }
        }
        return;
    }

    #pragma unroll
    for (int j = 0; j < 8; j++) {
        int c0 = n0 + 8 * j + 2 * t;
        float b0 = bias[c0], b1 = bias[c0 + 1];
        float v00 = acc[j][0] + b0, v01 = acc[j][1] + b1;
        float v10 = acc[j][2] + b0, v11 = acc[j][3] + b1;
        int r0 = m0 + rb + g, r1 = r0 + 8;
        if (do_rot) {
            float invf = expf(-(float)(c0 & (DH - 1)) * LNC);
            float sn, cs;
            sincosf((float)(r0 & (S_LEN - 1)) * invf, &sn, &cs);
            float x0 = v00, x1 = v01;
            v00 = x0 * cs - x1 * sn;  v01 = x1 * cs + x0 * sn;
            sincosf((float)(r1 & (S_LEN - 1)) * invf, &sn, &cs);
            x0 = v10; x1 = v11;
            v10 = x0 * cs - x1 * sn;  v11 = x1 * cs + x0 * sn;
        }
        v00 *= scale; v01 *= scale; v10 *= scale; v11 *= scale;

        if (dst_sel == 3) {
            *(float2*)(outp + (size_t)r0 * DIMN + c0) = make_float2(v00, v01);
            *(float2*)(outp + (size_t)r1 * DIMN + c0) = make_float2(v10, v11);
        } else {
            u32* dh = (u32*)(dst_sel ? g_khi : g_qhi);
            u32* dl = (u32*)(dst_sel ? g_klo : g_qlo);
            int hh = c0 >> 6, jd = c0 & (DH - 1);
            int bl = m0 >> 11;
            size_t i0 = (((size_t)(bl * NH + hh) * S_LEN + (r0 & (S_LEN - 1))) * DH + jd) >> 1;
            size_t i1 = (((size_t)(bl * NH + hh) * S_LEN + (r1 & (S_LEN - 1))) * DH + jd) >> 1;
            float h00 = bfr(v00), h01 = bfr(v01), h10 = bfr(v10), h11 = bfr(v11);
            dh[i0] = pkbf(h00, h01);
            dl[i0] = pkbf(v00 - h00, v01 - h01);
            dh[i1] = pkbf(h10, h11);
            dl[i1] = pkbf(v10 - h10, v11 - h11);
        }
    }
}

// Fused projection GEMMs: blockIdx.z selects {Q from Wq, K from Wv, V^T from Wk}
__global__ __launch_bounds__(256, 2)
void proj_gemm(const float* __restrict__ bq,
               const float* __restrict__ bk,
               const float* __restrict__ bv)
{
    extern __shared__ __align__(16) __nv_bfloat16 dsm[];
    const int z = blockIdx.z;
    const int widx = (z == 0) ? 0 : (z == 1) ? 2 : 1;
    const float* bias = (z == 0) ? bq : (z == 1) ? bv : bk;
    gemm_body(dsm, bias, nullptr, widx, z, (z != 2) ? 1 : 0,
              (z == 0) ? QSCALE : 1.0f, 0);
}

// Final output GEMM: inter @ Wo^T + bo
__global__ __launch_bounds__(256, 2)
void out_gemm(const float* __restrict__ bo, float* __restrict__ outp)
{
    extern __shared__ __align__(16) __nv_bfloat16 dsm[];
    gemm_body(dsm, bo, outp, 3, 3, 0, 1.0f, 1);
}

// ---------------------------------------------------------------------------
// Flash attention via HMMA: causal, no-max softmax, ones-column row sums.
// S = 2-term split, PV = 3-term split. 2-stage cp.async, ONE barrier per
// key-block, 2 CTAs/SM (register diet: no ldsm ping-pong; PRMT P packing).
// ---------------------------------------------------------------------------
#define ASTAGE_B 41472     // per stage: Kh 0, Kl 9216, Vh 18432, Vl 29952
__global__ __launch_bounds__(256, 2)
void attn_mma()
{
    extern __shared__ __align__(16) __nv_bfloat16 dsm[];

    const int blh  = blockIdx.y;
    const int qblk = gridDim.x - 1 - blockIdx.x;   // heavy-first
    const int q0   = qblk * 128;
    const int tid  = threadIdx.x;
    const int warp = tid >> 5, lane = tid & 31;
    const int g = lane >> 2, t = lane & 3;
    const u32 smb = smem_u32(dsm);

    const int rB = (lane >> 4) * 8 + (lane & 7);
    const int cB = ((lane >> 3) & 1) * 8;

    const __nv_bfloat16* Kbh = g_khi + (size_t)blh * S_LEN * DH;
    const __nv_bfloat16* Kbl = g_klo + (size_t)blh * S_LEN * DH;
    const __nv_bfloat16* Vbh = g_vthi + (size_t)blh * VROWS * S_LEN;
    const __nv_bfloat16* Vbl = g_vtlo + (size_t)blh * VROWS * S_LEN;

    // Q hi fragments only (2-term S split)
    u32 qa_h[4][4];
    {
        const u32* qh = (const u32*)(g_qhi + ((size_t)blh * S_LEN + q0 + warp * 16) * DH);
        #pragma unroll
        for (int k = 0; k < 4; k++) {
            qa_h[k][0] = qh[(g)     * 32 + k * 8 + t];
            qa_h[k][1] = qh[(g + 8) * 32 + k * 8 + t];
            qa_h[k][2] = qh[(g)     * 32 + k * 8 + 4 + t];
            qa_h[k][3] = qh[(g + 8) * 32 + k * 8 + 4 + t];
        }
    }

    float accO[9][4];
    #pragma unroll
    for (int j = 0; j < 9; j++)
        #pragma unroll
        for (int d = 0; d < 4; d++) accO[j][d] = 0.f;

    const int rmin  = q0 + warp * 16;
    const int kbmax = (q0 + 127) >> 6;

    auto prefetch = [&](int kb, int st) {
        u32 sb = smb + st * ASTAGE_B;
        #pragma unroll
        for (int i = 0; i < 2; i++) {
            int idx = i * 256 + tid;
            int row = idx >> 3, c = idx & 7;
            cpa16(sb + (row * 72 + c * 8) * 2,
                  Kbh + (size_t)(kb * 64 + row) * DH + c * 8);
            cpa16(sb + 9216 + (row * 72 + c * 8) * 2,
                  Kbl + (size_t)(kb * 64 + row) * DH + c * 8);
        }
        #pragma unroll
        for (int i = 0; i < 3; i++) {
            int idx = i * 256 + tid;
            if (idx < 640) {
                int row = idx >> 3, c = idx & 7;
                cpa16(sb + 18432 + (row * 72 + c * 8) * 2,
                      Vbh + (size_t)row * S_LEN + kb * 64 + c * 8);
                cpa16(sb + 29952 + (row * 72 + c * 8) * 2,
                      Vbl + (size_t)row * S_LEN + kb * 64 + c * 8);
            }
        }
        cpcommit();
    };

    prefetch(0, 0);

    for (int kb = 0; kb <= kbmax; kb++) {
        int st = kb & 1;
        cpwait0();                 // stage kb landed (committed >=1 iter ago)
        __syncthreads();           // all warps done reading stage kb^1
        if (kb + 1 <= kbmax) prefetch(kb + 1, st ^ 1);

        if (kb * 64 > rmin + 15) continue;

        u32 sb = smb + st * ASTAGE_B;
        u32 kH = sb + (rB * 72 + cB) * 2;
        u32 kL = kH + 9216;
        u32 vH = sb + 18432 + (rB * 72 + cB) * 2;
        u32 vL = vH + 11520;

        // ---- S = Q_hi (K_hi + K_lo)  (2-term split) ----
        float s[8][4];
        #pragma unroll
        for (int j = 0; j < 8; j++)
            #pragma unroll
            for (int d = 0; d < 4; d++) s[j][d] = 0.f;

        #pragma unroll
        for (int kk = 0; kk < 4; kk++)
            #pragma unroll
            for (int j2 = 0; j2 < 4; j2++) {
                u32 bh[4], bl[4];
                ldsm4(bh, kH + j2 * (16 * 72 * 2) + kk * 32);
                ldsm4(bl, kL + j2 * (16 * 72 * 2) + kk * 32);
                mmab(s[2 * j2],     qa_h[kk], bh[0], bh[1]);
                mmab(s[2 * j2],     qa_h[kk], bl[0], bl[1]);
                mmab(s[2 * j2 + 1], qa_h[kk], bh[2], bh[3]);
                mmab(s[2 * j2 + 1], qa_h[kk], bl[2], bl[3]);
            }

        // ---- softmax (no max) + P split: trunc hi (PRMT) + exact lo ----
        u32 pa_h[4][4], pa_l[4][4];
        const bool diag = (kb * 64 + 63 > rmin);
        #pragma unroll
        for (int j = 0; j < 8; j++) {
            float p0 = __expf(s[j][0]);
            float p1 = __expf(s[j][1]);
            float p2 = __expf(s[j][2]);
            float p3 = __expf(s[j][3]);
            if (diag) {
                int c0 = kb * 64 + 8 * j + 2 * t;
                int r0 = rmin + g, r1 = r0 + 8;
                if (c0     > r0) p0 = 0.f;
                if (c0 + 1 > r0) p1 = 0.f;
                if (c0     > r1) p2 = 0.f;
                if (c0 + 1 > r1) p3 = 0.f;
            }
            u32 u0 = __float_as_uint(p0), u1 = __float_as_uint(p1);
            u32 u2 = __float_as_uint(p2), u3 = __float_as_uint(p3);
            int kk = j >> 1, hh = (j & 1) * 2;
            pa_h[kk][hh]     = prmt_hi(u0, u1);
            pa_h[kk][hh + 1] = prmt_hi(u2, u3);
            float l0 = p0 - __uint_as_float(u0 & 0xFFFF0000u);
            float l1 = p1 - __uint_as_float(u1 & 0xFFFF0000u);
            float l2 = p2 - __uint_as_float(u2 & 0xFFFF0000u);
            float l3 = p3 - __uint_as_float(u3 & 0xFFFF0000u);
            pa_l[kk][hh]     = pkbf(l0, l1);
            pa_l[kk][hh + 1] = pkbf(l2, l3);
        }

        // ---- O += P V (3-term split); ones-column accumulates row sums ----
        #pragma unroll
        for (int kk = 0; kk < 4; kk++)
            #pragma unroll
            for (int j2 = 0; j2 < 5; j2++) {
                u32 vh[4], vl[4];
                ldsm4(vh, vH + j2 * (16 * 72 * 2) + kk * 32);
                ldsm4(vl, vL + j2 * (16 * 72 * 2) + kk * 32);
                mmab(accO[2 * j2], pa_h[kk], vh[0], vh[1]);
                mmab(accO[2 * j2], pa_h[kk], vl[0], vl[1]);
                mmab(accO[2 * j2], pa_l[kk], vh[0], vh[1]);
                if (j2 < 4) {
                    mmab(accO[2 * j2 + 1], pa_h[kk], vh[2], vh[3]);
                    mmab(accO[2 * j2 + 1], pa_h[kk], vl[2], vl[3]);
                    mmab(accO[2 * j2 + 1], pa_l[kk], vh[2], vh[3]);
                }
            }
    }

    // ---- finalize: divide by row sums (frag j=8, n=64), split, store ----
    float l0 = __shfl_sync(0xffffffffu, accO[8][0], lane & ~3);
    float l1 = __shfl_sync(0xffffffffu, accO[8][2], lane & ~3);
    float inv0 = 1.f / l0, inv1 = 1.f / l1;

    const int bl = blh >> 3, h = blh & 7;
    const int r0 = q0 + warp * 16 + g;
    u32* ih = (u32*)g_ihi;
    u32* il = (u32*)g_ilo;
    #pragma unroll
    for (int j = 0; j < 8; j++) {
        int c = h * DH + 8 * j + 2 * t;
        float o0 = accO[j][0] * inv0, o1 = accO[j][1] * inv0;
        float o2 = accO[j][2] * inv1, o3 = accO[j][3] * inv1;
        float h0 = bfr(o0), h1 = bfr(o1), h2 = bfr(o2), h3 = bfr(o3);
        size_t i0 = ((size_t)(bl * S_LEN + r0)) * 256 + (c >> 1);
        size_t i1 = ((size_t)(bl * S_LEN + r0 + 8)) * 256 + (c >> 1);
        ih[i0] = pkbf(h0, h1);
        il[i0] = pkbf(o0 - h0, o1 - h1);
        ih[i1] = pkbf(h2, h3);
        il[i1] = pkbf(o2 - h2, o3 - h3);
    }
}

// ---------------------------------------------------------------------------
extern "C" void kernel_launch(void* const* d_in, const int* in_sizes, int n_in,
                              void* d_out, int out_size)
{
    const float* x  = (const float*)d_in[0];
    const float* Wq = (const float*)d_in[1];
    const float* bq = (const float*)d_in[2];
    const float* Wk = (const float*)d_in[3];
    const float* bk = (const float*)d_in[4];
    const float* Wv = (const float*)d_in[5];
    const float* bv = (const float*)d_in[6];
    const float* Wo = (const float*)d_in[7];
    const float* bo = (const float*)d_in[8];
    float* out = (float*)d_out;

    cudaFuncSetAttribute(proj_gemm, cudaFuncAttributeMaxDynamicSharedMemorySize,
                         3 * GSTAGE_B);
    cudaFuncSetAttribute(out_gemm, cudaFuncAttributeMaxDynamicSharedMemorySize,
                         3 * GSTAGE_B);
    cudaFuncSetAttribute(attn_mma, cudaFuncAttributeMaxDynamicSharedMemorySize,
                         2 * ASTAGE_B);

    // 1: all splits + V^T ones rows, fused
    prep_kernel<<<24576, 256>>>(x, Wq, Wk, Wv, Wo);

    // 2: all three projections fused (z: 0=Q from Wq, 1=K from Wv, 2=V^T from Wk)
    proj_gemm<<<dim3(DIMN / 64, MTOT / 128, 3), 256, 3 * GSTAGE_B>>>(bq, bk, bv);

    // 3: attention (2 CTAs/SM)
    attn_mma<<<dim3(S_LEN / 128, NBLH), 256, 2 * ASTAGE_B>>>();

    // 4: inter @ Wo^T + bo
    out_gemm<<<dim3(DIMN / 64, MTOT / 128), 256, 3 * GSTAGE_B>>>(bo, out);
}

// round 17
// speedup vs baseline: 1.0152x; 1.0152x over previous
#include <cuda_runtime.h>
#include <cuda_bf16.h>

typedef unsigned int u32;

#define S_LEN 2048
#define DIMN  512
#define NH    8
#define DH    64
#define MTOT  8192
#define NBLH  32
#define VROWS 80          // 64 d-rows + ones row (64) + 15 zero pad rows
#define QSCALE 0.04419417382415922f   // 1/sqrt(512)
#define LNC 0.14391156831212787f      // ln(10000)/64

// ---------------------------------------------------------------------------
// Scratch (allocation-free device globals), bf16 hi/lo pairs
// ---------------------------------------------------------------------------
__device__ __align__(16) __nv_bfloat16 g_xhi[MTOT * DIMN],  g_xlo[MTOT * DIMN];
__device__ __align__(16) __nv_bfloat16 g_whi[4 * DIMN * DIMN], g_wlo[4 * DIMN * DIMN];
__device__ __align__(16) __nv_bfloat16 g_qhi[NBLH * S_LEN * DH], g_qlo[NBLH * S_LEN * DH];
__device__ __align__(16) __nv_bfloat16 g_khi[NBLH * S_LEN * DH], g_klo[NBLH * S_LEN * DH];
__device__ __align__(16) __nv_bfloat16 g_vthi[NBLH * VROWS * S_LEN], g_vtlo[NBLH * VROWS * S_LEN];
__device__ __align__(16) __nv_bfloat16 g_ihi[MTOT * DIMN],  g_ilo[MTOT * DIMN];

// ---------------------------------------------------------------------------
// Helpers
// ---------------------------------------------------------------------------
__device__ __forceinline__ u32 pkbf(float a, float b) {   // a->lo, b->hi
    u32 r;
    asm("cvt.rn.bf16x2.f32 %0, %1, %2;" : "=r"(r) : "f"(b), "f"(a));
    return r;
}
__device__ __forceinline__ float bfr(float v) {
    return __bfloat162float(__float2bfloat16(v));
}
__device__ __forceinline__ void mmab(float* d, const u32* a, u32 b0, u32 b1) {
    asm volatile(
        "mma.sync.aligned.m16n8k16.row.col.f32.bf16.bf16.f32 "
        "{%0,%1,%2,%3}, {%4,%5,%6,%7}, {%8,%9}, {%0,%1,%2,%3};"
        : "+f"(d[0]), "+f"(d[1]), "+f"(d[2]), "+f"(d[3])
        : "r"(a[0]), "r"(a[1]), "r"(a[2]), "r"(a[3]), "r"(b0), "r"(b1));
}
__device__ __forceinline__ u32 smem_u32(const void* p) {
    u32 a;
    asm("{ .reg .u64 t; cvta.to.shared.u64 t, %1; cvt.u32.u64 %0, t; }"
        : "=r"(a) : "l"(p));
    return a;
}
__device__ __forceinline__ void cpa16(u32 dst, const void* src) {
    asm volatile("cp.async.cg.shared.global [%0], [%1], 16;" :: "r"(dst), "l"(src));
}
__device__ __forceinline__ void cpcommit() {
    asm volatile("cp.async.commit_group;" ::: "memory");
}
__device__ __forceinline__ void cpwait1() {
    asm volatile("cp.async.wait_group 1;" ::: "memory");
}
__device__ __forceinline__ void cpwait0() {
    asm volatile("cp.async.wait_group 0;" ::: "memory");
}
__device__ __forceinline__ void ldsm4(u32* r, u32 a) {
    asm volatile("ldmatrix.sync.aligned.m8n8.x4.shared.b16 {%0,%1,%2,%3}, [%4];"
                 : "=r"(r[0]), "=r"(r[1]), "=r"(r[2]), "=r"(r[3]) : "r"(a));
}

// ---------------------------------------------------------------------------
// Fused prep: all fp32->bf16 hi/lo splits + V^T ones/pad rows, one launch.
// ---------------------------------------------------------------------------
__global__ __launch_bounds__(256)
void prep_kernel(const float* __restrict__ x,
                 const float* __restrict__ Wq, const float* __restrict__ Wk,
                 const float* __restrict__ Wv, const float* __restrict__ Wo)
{
    int b = blockIdx.x;
    int tid = threadIdx.x;
    if (b < 16384) {
        int i = b * 256 + tid;
        float v = x[i];
        __nv_bfloat16 h = __float2bfloat16(v);
        g_xhi[i] = h;
        g_xlo[i] = __float2bfloat16(v - __bfloat162float(h));
    } else if (b < 20480) {
        int b2 = b - 16384;
        int widx = b2 >> 10;
        int i = (b2 & 1023) * 256 + tid;
        const float* W = widx == 0 ? Wq : widx == 1 ? Wk : widx == 2 ? Wv : Wo;
        float v = W[i];
        __nv_bfloat16 h = __float2bfloat16(v);
        size_t o = (size_t)widx * DIMN * DIMN + i;
        g_whi[o] = h;
        g_wlo[o] = __float2bfloat16(v - __bfloat162float(h));
    } else {
        int idx = (b - 20480) * 256 + tid;
        int s   = idx & (S_LEN - 1);
        int rr  = (idx >> 11) & 15;
        int blh = idx >> 15;
        size_t a = ((size_t)blh * VROWS + 64 + rr) * S_LEN + s;
        g_vthi[a] = __float2bfloat16(rr == 0 ? 1.0f : 0.0f);
        g_vtlo[a] = __float2bfloat16(0.0f);
    }
}

// ---------------------------------------------------------------------------
// Common GEMM body (R12/R14 config): tile M=128 x N=64, k-step 32,
// 3-stage cp.async, ONE barrier per k-step, ldsm-pipelined, 3-term split.
// dst_sel: 0 Q(blh,s,dh)  1 K(blh,s,dh)  2 V^T(blh,80,s)  3 fp32 out(m,512)
// ---------------------------------------------------------------------------
#define GSTAGE_B 30720     // per stage: Ah 0 | Al 10240 | Wh 20480 | Wl 25600
__device__ __forceinline__
void gemm_body(__nv_bfloat16* dsm,
               const float* __restrict__ bias,
               float* __restrict__ outp,
               int widx, int dst_sel, int do_rot, float scale, int src_sel)
{
    const __nv_bfloat16* Ahg = src_sel ? g_ihi : g_xhi;
    const __nv_bfloat16* Alg = src_sel ? g_ilo : g_xlo;
    const __nv_bfloat16* Whg = g_whi + (size_t)widx * DIMN * DIMN;
    const __nv_bfloat16* Wlg = g_wlo + (size_t)widx * DIMN * DIMN;

    const int n0 = blockIdx.x * 64;
    const int m0 = blockIdx.y * 128;
    const int tid = threadIdx.x;
    const int warp = tid >> 5, lane = tid & 31;
    const int g = lane >> 2, t = lane & 3;
    const u32 smb = smem_u32(dsm);

    const int rA = ((lane >> 3) & 1) * 8 + (lane & 7);
    const int cA = ((lane >> 4) & 1) * 8;
    const int rB = (lane >> 4) * 8 + (lane & 7);
    const int cB = ((lane >> 3) & 1) * 8;

    float acc[8][4];
    #pragma unroll
    for (int j = 0; j < 8; j++)
        #pragma unroll
        for (int d = 0; d < 4; d++) acc[j][d] = 0.f;

    auto prefetch = [&](int kt, int st) {
        u32 sb = smb + st * GSTAGE_B;
        int k0 = kt * 32;
        #pragma unroll
        for (int i = 0; i < 2; i++) {
            int idx = i * 256 + tid;
            int row = idx >> 2, c = idx & 3;
            cpa16(sb + (row * 40 + c * 8) * 2,
                  Ahg + (size_t)(m0 + row) * DIMN + k0 + c * 8);
            cpa16(sb + 10240 + (row * 40 + c * 8) * 2,
                  Alg + (size_t)(m0 + row) * DIMN + k0 + c * 8);
        }
        {
            int row = tid >> 2, c = tid & 3;
            cpa16(sb + 20480 + (row * 40 + c * 8) * 2,
                  Whg + (size_t)(n0 + row) * DIMN + k0 + c * 8);
            cpa16(sb + 25600 + (row * 40 + c * 8) * 2,
                  Wlg + (size_t)(n0 + row) * DIMN + k0 + c * 8);
        }
        cpcommit();
    };

    prefetch(0, 0);
    prefetch(1, 1);

    for (int kt = 0; kt < 16; kt++) {
        int st = kt % 3;
        if (kt < 15) cpwait1(); else cpwait0();
        __syncthreads();
        if (kt + 2 < 16) prefetch(kt + 2, (kt + 2) % 3);

        u32 sb = smb + st * GSTAGE_B;
        u32 aHb = sb + ((warp * 16 + rA) * 40 + cA) * 2;
        u32 aLb = aHb + 10240;
        u32 bHb = sb + 20480 + (rB * 40 + cB) * 2;
        u32 bLb = bHb + 5120;

        u32 ah[2][4], al[2][4];
        ldsm4(ah[0], aHb);      ldsm4(al[0], aLb);
        ldsm4(ah[1], aHb + 32); ldsm4(al[1], aLb + 32);
        u32 bh[2][4], bl[2][4];
        ldsm4(bh[0], bHb);      ldsm4(bl[0], bLb);

        #pragma unroll
        for (int idx = 0; idx < 8; idx++) {
            const int kk = idx >> 2, j2 = idx & 3;
            const int p = idx & 1;
            if (idx < 7) {
                const int ni = idx + 1, nkk = ni >> 2, nj2 = ni & 3;
                ldsm4(bh[p ^ 1], bHb + nj2 * (16 * 40 * 2) + nkk * 32);
                ldsm4(bl[p ^ 1], bLb + nj2 * (16 * 40 * 2) + nkk * 32);
            }
            mmab(acc[2 * j2],     ah[kk], bh[p][0], bh[p][1]);
            mmab(acc[2 * j2],     ah[kk], bl[p][0], bl[p][1]);
            mmab(acc[2 * j2],     al[kk], bh[p][0], bh[p][1]);
            mmab(acc[2 * j2 + 1], ah[kk], bh[p][2], bh[p][3]);
            mmab(acc[2 * j2 + 1], ah[kk], bl[p][2], bl[p][3]);
            mmab(acc[2 * j2 + 1], al[kk], bh[p][2], bh[p][3]);
        }
    }

    // ---- Epilogue ----
    const int rb = warp * 16;

    if (dst_sel == 2) {
        // V^T: transpose via smem (two passes: hi then lo)
        __nv_bfloat16* T = dsm;   // 64 x 136
        const int bl = m0 >> 11, hh = n0 >> 6;
        const int s0 = m0 & (S_LEN - 1);
        #pragma unroll
        for (int pass = 0; pass < 2; pass++) {
            __syncthreads();
            #pragma unroll
            for (int j = 0; j < 8; j++) {
                int cl0 = 8 * j + 2 * t;
                float b0 = bias[n0 + cl0], b1 = bias[n0 + cl0 + 1];
                float v00 = acc[j][0] + b0, v01 = acc[j][1] + b1;
                float v10 = acc[j][2] + b0, v11 = acc[j][3] + b1;
                float e00, e01, e10, e11;
                if (pass == 0) { e00 = v00; e01 = v01; e10 = v10; e11 = v11; }
                else { e00 = v00 - bfr(v00); e01 = v01 - bfr(v01);
                       e10 = v10 - bfr(v10); e11 = v11 - bfr(v11); }
                T[(cl0)     * 136 + rb + g]     = __float2bfloat16(e00);
                T[(cl0 + 1) * 136 + rb + g]     = __float2bfloat16(e01);
                T[(cl0)     * 136 + rb + g + 8] = __float2bfloat16(e10);
                T[(cl0 + 1) * 136 + rb + g + 8] = __float2bfloat16(e11);
            }
            __syncthreads();
            __nv_bfloat16* dst = pass ? g_vtlo : g_vthi;
            size_t base = ((size_t)(bl * NH + hh)) * VROWS * S_LEN + s0;
            #pragma unroll
            for (int w8 = 0; w8 < 4; w8++) {
                int idx = w8 * 256 + tid;
                int row = idx >> 4, c8 = idx & 15;
                *(uint4*)(dst + base + (size_t)row * S_LEN + c8 * 8) =
                    *(const uint4*)(T + row * 136 + c8 * 8);
            }
        }
        return;
    }

    #pragma unroll
    for (int j = 0; j < 8; j++) {
        int c0 = n0 + 8 * j + 2 * t;
        float b0 = bias[c0], b1 = bias[c0 + 1];
        float v00 = acc[j][0] + b0, v01 = acc[j][1] + b1;
        float v10 = acc[j][2] + b0, v11 = acc[j][3] + b1;
        int r0 = m0 + rb + g, r1 = r0 + 8;
        if (do_rot) {
            float invf = expf(-(float)(c0 & (DH - 1)) * LNC);
            float sn, cs;
            sincosf((float)(r0 & (S_LEN - 1)) * invf, &sn, &cs);
            float x0 = v00, x1 = v01;
            v00 = x0 * cs - x1 * sn;  v01 = x1 * cs + x0 * sn;
            sincosf((float)(r1 & (S_LEN - 1)) * invf, &sn, &cs);
            x0 = v10; x1 = v11;
            v10 = x0 * cs - x1 * sn;  v11 = x1 * cs + x0 * sn;
        }
        v00 *= scale; v01 *= scale; v10 *= scale; v11 *= scale;

        if (dst_sel == 3) {
            *(float2*)(outp + (size_t)r0 * DIMN + c0) = make_float2(v00, v01);
            *(float2*)(outp + (size_t)r1 * DIMN + c0) = make_float2(v10, v11);
        } else {
            u32* dh = (u32*)(dst_sel ? g_khi : g_qhi);
            u32* dl = (u32*)(dst_sel ? g_klo : g_qlo);
            int hh = c0 >> 6, jd = c0 & (DH - 1);
            int bl = m0 >> 11;
            size_t i0 = (((size_t)(bl * NH + hh) * S_LEN + (r0 & (S_LEN - 1))) * DH + jd) >> 1;
            size_t i1 = (((size_t)(bl * NH + hh) * S_LEN + (r1 & (S_LEN - 1))) * DH + jd) >> 1;
            float h00 = bfr(v00), h01 = bfr(v01), h10 = bfr(v10), h11 = bfr(v11);
            dh[i0] = pkbf(h00, h01);
            dl[i0] = pkbf(v00 - h00, v01 - h01);
            dh[i1] = pkbf(h10, h11);
            dl[i1] = pkbf(v10 - h10, v11 - h11);
        }
    }
}

// Fused projection GEMMs: blockIdx.z selects {Q from Wq, K from Wv, V^T from Wk}
__global__ __launch_bounds__(256, 2)
void proj_gemm(const float* __restrict__ bq,
               const float* __restrict__ bk,
               const float* __restrict__ bv)
{
    extern __shared__ __align__(16) __nv_bfloat16 dsm[];
    const int z = blockIdx.z;
    const int widx = (z == 0) ? 0 : (z == 1) ? 2 : 1;
    const float* bias = (z == 0) ? bq : (z == 1) ? bv : bk;
    gemm_body(dsm, bias, nullptr, widx, z, (z != 2) ? 1 : 0,
              (z == 0) ? QSCALE : 1.0f, 0);
}

// Final output GEMM: inter @ Wo^T + bo
__global__ __launch_bounds__(256, 2)
void out_gemm(const float* __restrict__ bo, float* __restrict__ outp)
{
    extern __shared__ __align__(16) __nv_bfloat16 dsm[];
    gemm_body(dsm, bo, outp, 3, 3, 0, 1.0f, 1);
}

// ---------------------------------------------------------------------------
// Flash attention via HMMA (R14 config, full-size stages): causal, no-max
// softmax, ones-column row sums. S = 2-term split, PV = 3-term split.
// 3-stage cp.async, ONE barrier per key-block, ldsm-pipelined, 1 CTA/SM.
// Only change vs R14: skip the pa_h*V_lo MMA for the ones/pad fragment
// (j2==4) — that V_lo tile is exactly zero, so this is bit-identical.
// ---------------------------------------------------------------------------
#define ASTAGE_B 41472     // per stage: Kh 0, Kl 9216, Vh 18432, Vl 29952
__global__ __launch_bounds__(256, 1)
void attn_mma()
{
    extern __shared__ __align__(16) __nv_bfloat16 dsm[];

    const int blh  = blockIdx.y;
    const int qblk = gridDim.x - 1 - blockIdx.x;   // heavy-first
    const int q0   = qblk * 128;
    const int tid  = threadIdx.x;
    const int warp = tid >> 5, lane = tid & 31;
    const int g = lane >> 2, t = lane & 3;
    const u32 smb = smem_u32(dsm);

    const int rB = (lane >> 4) * 8 + (lane & 7);
    const int cB = ((lane >> 3) & 1) * 8;

    const __nv_bfloat16* Kbh = g_khi + (size_t)blh * S_LEN * DH;
    const __nv_bfloat16* Kbl = g_klo + (size_t)blh * S_LEN * DH;
    const __nv_bfloat16* Vbh = g_vthi + (size_t)blh * VROWS * S_LEN;
    const __nv_bfloat16* Vbl = g_vtlo + (size_t)blh * VROWS * S_LEN;

    // Q hi fragments only (2-term S split)
    u32 qa_h[4][4];
    {
        const u32* qh = (const u32*)(g_qhi + ((size_t)blh * S_LEN + q0 + warp * 16) * DH);
        #pragma unroll
        for (int k = 0; k < 4; k++) {
            qa_h[k][0] = qh[(g)     * 32 + k * 8 + t];
            qa_h[k][1] = qh[(g + 8) * 32 + k * 8 + t];
            qa_h[k][2] = qh[(g)     * 32 + k * 8 + 4 + t];
            qa_h[k][3] = qh[(g + 8) * 32 + k * 8 + 4 + t];
        }
    }

    float accO[9][4];
    #pragma unroll
    for (int j = 0; j < 9; j++)
        #pragma unroll
        for (int d = 0; d < 4; d++) accO[j][d] = 0.f;

    const int rmin  = q0 + warp * 16;
    const int kbmax = (q0 + 127) >> 6;

    auto prefetch = [&](int kb, int st) {
        u32 sb = smb + st * ASTAGE_B;
        #pragma unroll
        for (int i = 0; i < 2; i++) {
            int idx = i * 256 + tid;
            int row = idx >> 3, c = idx & 7;
            cpa16(sb + (row * 72 + c * 8) * 2,
                  Kbh + (size_t)(kb * 64 + row) * DH + c * 8);
            cpa16(sb + 9216 + (row * 72 + c * 8) * 2,
                  Kbl + (size_t)(kb * 64 + row) * DH + c * 8);
        }
        #pragma unroll
        for (int i = 0; i < 3; i++) {
            int idx = i * 256 + tid;
            if (idx < 640) {
                int row = idx >> 3, c = idx & 7;
                cpa16(sb + 18432 + (row * 72 + c * 8) * 2,
                      Vbh + (size_t)row * S_LEN + kb * 64 + c * 8);
                cpa16(sb + 29952 + (row * 72 + c * 8) * 2,
                      Vbl + (size_t)row * S_LEN + kb * 64 + c * 8);
            }
        }
        cpcommit();
    };

    prefetch(0, 0);
    if (kbmax >= 1) prefetch(1, 1);

    for (int kb = 0; kb <= kbmax; kb++) {
        int st = kb % 3;
        if (kb < kbmax) cpwait1(); else cpwait0();
        __syncthreads();
        if (kb + 2 <= kbmax) prefetch(kb + 2, (kb + 2) % 3);

        if (kb * 64 > rmin + 15) continue;

        u32 sb = smb + st * ASTAGE_B;
        u32 kH = sb + (rB * 72 + cB) * 2;
        u32 kL = kH + 9216;
        u32 vH = sb + 18432 + (rB * 72 + cB) * 2;
        u32 vL = vH + 11520;

        // ---- S = Q_hi (K_hi + K_lo)  (2-term split, ldsm-pipelined) ----
        float s[8][4];
        #pragma unroll
        for (int j = 0; j < 8; j++)
            #pragma unroll
            for (int d = 0; d < 4; d++) s[j][d] = 0.f;

        {
            u32 bh[2][4], bl[2][4];
            ldsm4(bh[0], kH); ldsm4(bl[0], kL);
            #pragma unroll
            for (int idx = 0; idx < 16; idx++) {
                const int kk = idx >> 2, j2 = idx & 3;
                const int p = idx & 1;
                if (idx < 15) {
                    const int ni = idx + 1, nkk = ni >> 2, nj2 = ni & 3;
                    ldsm4(bh[p ^ 1], kH + nj2 * (16 * 72 * 2) + nkk * 32);
                    ldsm4(bl[p ^ 1], kL + nj2 * (16 * 72 * 2) + nkk * 32);
                }
                mmab(s[2 * j2],     qa_h[kk], bh[p][0], bh[p][1]);
                mmab(s[2 * j2],     qa_h[kk], bl[p][0], bl[p][1]);
                mmab(s[2 * j2 + 1], qa_h[kk], bh[p][2], bh[p][3]);
                mmab(s[2 * j2 + 1], qa_h[kk], bl[p][2], bl[p][3]);
            }
        }

        // ---- softmax (no max) + in-register P hi/lo fragment build ----
        u32 pa_h[4][4], pa_l[4][4];
        const bool diag = (kb * 64 + 63 > rmin);
        #pragma unroll
        for (int j = 0; j < 8; j++) {
            float p0 = __expf(s[j][0]);
            float p1 = __expf(s[j][1]);
            float p2 = __expf(s[j][2]);
            float p3 = __expf(s[j][3]);
            if (diag) {
                int c0 = kb * 64 + 8 * j + 2 * t;
                int r0 = rmin + g, r1 = r0 + 8;
                if (c0     > r0) p0 = 0.f;
                if (c0 + 1 > r0) p1 = 0.f;
                if (c0     > r1) p2 = 0.f;
                if (c0 + 1 > r1) p3 = 0.f;
            }
            float h0 = bfr(p0), h1 = bfr(p1), h2 = bfr(p2), h3 = bfr(p3);
            int kk = j >> 1, hh = (j & 1) * 2;
            pa_h[kk][hh]     = pkbf(h0, h1);
            pa_h[kk][hh + 1] = pkbf(h2, h3);
            pa_l[kk][hh]     = pkbf(p0 - h0, p1 - h1);
            pa_l[kk][hh + 1] = pkbf(p2 - h2, p3 - h3);
        }

        // ---- O += P V (3-term split, ldsm-pipelined); ones-column sums ----
        // j2==4 fragment covers V rows 64..79: V_lo there is exactly zero,
        // so pa_h*vl is skipped (bit-identical, saves 4 MMAs per block).
        {
            u32 vh[2][4], vl[2][4];
            ldsm4(vh[0], vH); ldsm4(vl[0], vL);
            #pragma unroll
            for (int idx = 0; idx < 20; idx++) {
                const int kk = idx / 5, j2 = idx % 5;
                const int p = idx & 1;
                if (idx < 19) {
                    const int ni = idx + 1, nkk = ni / 5, nj2 = ni % 5;
                    ldsm4(vh[p ^ 1], vH + nj2 * (16 * 72 * 2) + nkk * 32);
                    ldsm4(vl[p ^ 1], vL + nj2 * (16 * 72 * 2) + nkk * 32);
                }
                mmab(accO[2 * j2], pa_h[kk], vh[p][0], vh[p][1]);
                if (j2 < 4) mmab(accO[2 * j2], pa_h[kk], vl[p][0], vl[p][1]);
                mmab(accO[2 * j2], pa_l[kk], vh[p][0], vh[p][1]);
                if (j2 < 4) {
                    mmab(accO[2 * j2 + 1], pa_h[kk], vh[p][2], vh[p][3]);
                    mmab(accO[2 * j2 + 1], pa_h[kk], vl[p][2], vl[p][3]);
                    mmab(accO[2 * j2 + 1], pa_l[kk], vh[p][2], vh[p][3]);
                }
            }
        }
    }

    // ---- finalize: divide by row sums (frag j=8, n=64), split, store ----
    float l0 = __shfl_sync(0xffffffffu, accO[8][0], lane & ~3);
    float l1 = __shfl_sync(0xffffffffu, accO[8][2], lane & ~3);
    float inv0 = 1.f / l0, inv1 = 1.f / l1;

    const int bl = blh >> 3, h = blh & 7;
    const int r0 = q0 + warp * 16 + g;
    u32* ih = (u32*)g_ihi;
    u32* il = (u32*)g_ilo;
    #pragma unroll
    for (int j = 0; j < 8; j++) {
        int c = h * DH + 8 * j + 2 * t;
        float o0 = accO[j][0] * inv0, o1 = accO[j][1] * inv0;
        float o2 = accO[j][2] * inv1, o3 = accO[j][3] * inv1;
        float h0 = bfr(o0), h1 = bfr(o1), h2 = bfr(o2), h3 = bfr(o3);
        size_t i0 = ((size_t)(bl * S_LEN + r0)) * 256 + (c >> 1);
        size_t i1 = ((size_t)(bl * S_LEN + r0 + 8)) * 256 + (c >> 1);
        ih[i0] = pkbf(h0, h1);
        il[i0] = pkbf(o0 - h0, o1 - h1);
        ih[i1] = pkbf(h2, h3);
        il[i1] = pkbf(o2 - h2, o3 - h3);
    }
}

// ---------------------------------------------------------------------------
extern "C" void kernel_launch(void* const* d_in, const int* in_sizes, int n_in,
                              void* d_out, int out_size)
{
    const float* x  = (const float*)d_in[0];
    const float* Wq = (const float*)d_in[1];
    const float* bq = (const float*)d_in[2];
    const float* Wk = (const float*)d_in[3];
    const float* bk = (const float*)d_in[4];
    const float* Wv = (const float*)d_in[5];
    const float* bv = (const float*)d_in[6];
    const float* Wo = (const float*)d_in[7];
    const float* bo = (const float*)d_in[8];
    float* out = (float*)d_out;

    cudaFuncSetAttribute(proj_gemm, cudaFuncAttributeMaxDynamicSharedMemorySize,
                         3 * GSTAGE_B);
    cudaFuncSetAttribute(out_gemm, cudaFuncAttributeMaxDynamicSharedMemorySize,
                         3 * GSTAGE_B);
    cudaFuncSetAttribute(attn_mma, cudaFuncAttributeMaxDynamicSharedMemorySize,
                         3 * ASTAGE_B);

    // 1: all splits + V^T ones rows, fused
    prep_kernel<<<24576, 256>>>(x, Wq, Wk, Wv, Wo);

    // 2: all three projections fused (z: 0=Q from Wq, 1=K from Wv, 2=V^T from Wk)
    proj_gemm<<<dim3(DIMN / 64, MTOT / 128, 3), 256, 3 * GSTAGE_B>>>(bq, bk, bv);

    // 3: attention
    attn_mma<<<dim3(S_LEN / 128, NBLH), 256, 3 * ASTAGE_B>>>();

    // 4: inter @ Wo^T + bo
    out_gemm<<<dim3(DIMN / 64, MTOT / 128), 256, 3 * GSTAGE_B>>>(bo, out);
}